// round 3
// baseline (speedup 1.0000x reference)
#include <cuda_runtime.h>

static constexpr int NTOK = 8192;
static constexpr int HID  = 256;

// Scratch (device globals — no allocation allowed in kernel_launch).
__device__ float g_support[NTOK * HID];  // x@W + b
__device__ float g_h[NTOK * HID];        // relu(adj @ support)

// ---------------------------------------------------------------------------
// Generic GEMM: C[M,N] = op(A[M,K] @ B[K,N] (+bias) (relu))
// Row-major, BM=128, BN=64, BK=16, 256 threads (16x16), microtile 8x4.
// Requires M%128==0, N%64==0, K%16==0 (true for all shapes here).
// ---------------------------------------------------------------------------
template<bool BIAS, bool RELU>
__global__ __launch_bounds__(256)
void gemm_128x64(const float* __restrict__ A, int lda,
                 const float* __restrict__ B, int ldb,
                 const float* __restrict__ bias,
                 float* __restrict__ C, int ldc, int K)
{
    __shared__ float As[16][128];   // transposed: As[k][row]
    __shared__ float Bs[16][64];    // Bs[k][col]

    const int tid = threadIdx.x;
    const int tx  = tid & 15;       // col group (4 cols each)
    const int ty  = tid >> 4;       // row group (8 rows each)
    const int bi  = blockIdx.y * 128;
    const int bj  = blockIdx.x * 64;

    // A tile loader: each thread loads 8 consecutive k-values of one row
    const int ar = tid >> 1;          // 0..127
    const int ac = (tid & 1) * 8;     // 0 or 8
    // B tile loader: each thread loads 4 consecutive cols of one k-row
    const int bk = tid >> 4;          // 0..15
    const int bn = (tid & 15) * 4;    // 0..60

    float acc[8][4];
    #pragma unroll
    for (int i = 0; i < 8; i++)
        #pragma unroll
        for (int j = 0; j < 4; j++) acc[i][j] = 0.f;

    const float* Ap = A + (long long)(bi + ar) * lda + ac;
    const float* Bp = B + (long long)bk * ldb + bj + bn;

    for (int k0 = 0; k0 < K; k0 += 16) {
        float4 a0 = *(const float4*)(Ap + k0);
        float4 a1 = *(const float4*)(Ap + k0 + 4);
        float4 b0 = *(const float4*)(Bp + (long long)k0 * ldb);

        As[ac + 0][ar] = a0.x; As[ac + 1][ar] = a0.y;
        As[ac + 2][ar] = a0.z; As[ac + 3][ar] = a0.w;
        As[ac + 4][ar] = a1.x; As[ac + 5][ar] = a1.y;
        As[ac + 6][ar] = a1.z; As[ac + 7][ar] = a1.w;
        *(float4*)&Bs[bk][bn] = b0;
        __syncthreads();

        #pragma unroll
        for (int k = 0; k < 16; k++) {
            float4 ra0 = *(const float4*)&As[k][ty * 8];
            float4 ra1 = *(const float4*)&As[k][ty * 8 + 4];
            float4 rb4 = *(const float4*)&Bs[k][tx * 4];
            float ra[8] = {ra0.x, ra0.y, ra0.z, ra0.w, ra1.x, ra1.y, ra1.z, ra1.w};
            float rb[4] = {rb4.x, rb4.y, rb4.z, rb4.w};
            #pragma unroll
            for (int i = 0; i < 8; i++)
                #pragma unroll
                for (int j = 0; j < 4; j++)
                    acc[i][j] = fmaf(ra[i], rb[j], acc[i][j]);
        }
        __syncthreads();
    }

    float4 bv = {0.f, 0.f, 0.f, 0.f};
    if (BIAS) bv = *(const float4*)&bias[bj + tx * 4];

    #pragma unroll
    for (int i = 0; i < 8; i++) {
        float4 v = {acc[i][0], acc[i][1], acc[i][2], acc[i][3]};
        if (BIAS) { v.x += bv.x; v.y += bv.y; v.z += bv.z; v.w += bv.w; }
        if (RELU) {
            v.x = fmaxf(v.x, 0.f); v.y = fmaxf(v.y, 0.f);
            v.z = fmaxf(v.z, 0.f); v.w = fmaxf(v.w, 0.f);
        }
        *(float4*)&C[(long long)(bi + ty * 8 + i) * ldc + bj + tx * 4] = v;
    }
}

// ---------------------------------------------------------------------------
// SYRK-style: C[NTOK,NTOK] = H @ H^T, exploiting symmetry.
// 128x128 tiles, 256 threads, 8x8 microtile. Blocks with bx<by exit early;
// off-diagonal blocks mirror their result with coalesced float4 stores.
// ---------------------------------------------------------------------------
__global__ __launch_bounds__(256)
void syrk_128x128(const float* __restrict__ H, float* __restrict__ C)
{
    if (blockIdx.x < blockIdx.y) return;   // upper triangle only

    __shared__ float As[16][128];   // As[k][row]   (rows bi..bi+127)
    __shared__ float Bs[16][128];   // Bs[k][col]   (rows bj..bj+127 of H)

    const int tid = threadIdx.x;
    const int tx  = tid & 15;
    const int ty  = tid >> 4;
    const int bi  = blockIdx.y * 128;
    const int bj  = blockIdx.x * 128;

    const int ar = tid >> 1;
    const int ac = (tid & 1) * 8;

    float acc[8][8];
    #pragma unroll
    for (int i = 0; i < 8; i++)
        #pragma unroll
        for (int j = 0; j < 8; j++) acc[i][j] = 0.f;

    const float* Ap = H + (long long)(bi + ar) * HID + ac;
    const float* Bp = H + (long long)(bj + ar) * HID + ac;

    for (int k0 = 0; k0 < HID; k0 += 16) {
        float4 a0 = *(const float4*)(Ap + k0);
        float4 a1 = *(const float4*)(Ap + k0 + 4);
        float4 c0 = *(const float4*)(Bp + k0);
        float4 c1 = *(const float4*)(Bp + k0 + 4);

        As[ac + 0][ar] = a0.x; As[ac + 1][ar] = a0.y;
        As[ac + 2][ar] = a0.z; As[ac + 3][ar] = a0.w;
        As[ac + 4][ar] = a1.x; As[ac + 5][ar] = a1.y;
        As[ac + 6][ar] = a1.z; As[ac + 7][ar] = a1.w;
        Bs[ac + 0][ar] = c0.x; Bs[ac + 1][ar] = c0.y;
        Bs[ac + 2][ar] = c0.z; Bs[ac + 3][ar] = c0.w;
        Bs[ac + 4][ar] = c1.x; Bs[ac + 5][ar] = c1.y;
        Bs[ac + 6][ar] = c1.z; Bs[ac + 7][ar] = c1.w;
        __syncthreads();

        #pragma unroll
        for (int k = 0; k < 16; k++) {
            float4 ra0 = *(const float4*)&As[k][ty * 8];
            float4 ra1 = *(const float4*)&As[k][ty * 8 + 4];
            float4 rb0 = *(const float4*)&Bs[k][tx * 8];
            float4 rb1 = *(const float4*)&Bs[k][tx * 8 + 4];
            float ra[8] = {ra0.x, ra0.y, ra0.z, ra0.w, ra1.x, ra1.y, ra1.z, ra1.w};
            float rb[8] = {rb0.x, rb0.y, rb0.z, rb0.w, rb1.x, rb1.y, rb1.z, rb1.w};
            #pragma unroll
            for (int i = 0; i < 8; i++)
                #pragma unroll
                for (int j = 0; j < 8; j++)
                    acc[i][j] = fmaf(ra[i], rb[j], acc[i][j]);
        }
        __syncthreads();
    }

    // Direct stores (upper-triangle block)
    #pragma unroll
    for (int i = 0; i < 8; i++) {
        const long long row = bi + ty * 8 + i;
        float4 v0 = {acc[i][0], acc[i][1], acc[i][2], acc[i][3]};
        float4 v1 = {acc[i][4], acc[i][5], acc[i][6], acc[i][7]};
        *(float4*)&C[row * NTOK + bj + tx * 8]     = v0;
        *(float4*)&C[row * NTOK + bj + tx * 8 + 4] = v1;
    }

    // Mirror to lower triangle (skip for diagonal blocks).
    // Per thread, column j of its microtile is 8 consecutive output elements
    // in the mirrored row -> two float4 stores, sector-coalesced.
    if (blockIdx.x != blockIdx.y) {
        #pragma unroll
        for (int j = 0; j < 8; j++) {
            const long long row = bj + tx * 8 + j;
            float4 v0 = {acc[0][j], acc[1][j], acc[2][j], acc[3][j]};
            float4 v1 = {acc[4][j], acc[5][j], acc[6][j], acc[7][j]};
            *(float4*)&C[row * NTOK + bi + ty * 8]     = v0;
            *(float4*)&C[row * NTOK + bi + ty * 8 + 4] = v1;
        }
    }
}

// ---------------------------------------------------------------------------
// Launch: inputs in metadata order: x[N,HID], adj[N,N], W[HID,HID], b[HID]
// ---------------------------------------------------------------------------
extern "C" void kernel_launch(void* const* d_in, const int* in_sizes, int n_in,
                              void* d_out, int out_size)
{
    const float* x   = (const float*)d_in[0];
    const float* adj = (const float*)d_in[1];
    const float* W   = (const float*)d_in[2];
    const float* b   = (const float*)d_in[3];
    float*       out = (float*)d_out;

    float* sup = nullptr;
    float* h   = nullptr;
    cudaGetSymbolAddress((void**)&sup, g_support);
    cudaGetSymbolAddress((void**)&h,   g_h);

    const dim3 blk(256);

    // 1) support = x @ W + b          (M=8192, N=256, K=256)
    gemm_128x64<true, false><<<dim3(HID / 64, NTOK / 128), blk>>>(
        x, HID, W, HID, b, sup, HID, HID);

    // 2) h = relu(adj @ support)      (M=8192, N=256, K=8192)
    gemm_128x64<false, true><<<dim3(HID / 64, NTOK / 128), blk>>>(
        adj, NTOK, sup, HID, nullptr, h, HID, NTOK);

    // 3) out = h @ h^T                (M=N=8192, K=256, symmetric)
    syrk_128x128<<<dim3(NTOK / 128, NTOK / 128), blk>>>(h, out);
}

// round 6
// speedup vs baseline: 1.7024x; 1.7024x over previous
#include <cuda_runtime.h>
#include <cuda_bf16.h>
#include <cstdint>

static constexpr int NTOK = 8192;
static constexpr int HID  = 256;

// ---------------- scratch (device globals; no allocation allowed) -----------
__device__ __align__(256) float         g_support[NTOK * HID];
__device__ __align__(256) __nv_bfloat16 g_adj_hi[(size_t)NTOK * NTOK];
__device__ __align__(256) __nv_bfloat16 g_adj_lo[(size_t)NTOK * NTOK];
__device__ __align__(256) __nv_bfloat16 g_supT_hi[(size_t)HID * NTOK];
__device__ __align__(256) __nv_bfloat16 g_supT_lo[(size_t)HID * NTOK];
__device__ __align__(256) __nv_bfloat16 g_h_hi[(size_t)NTOK * HID];
__device__ __align__(256) __nv_bfloat16 g_h_lo[(size_t)NTOK * HID];

// ---------------- PTX helpers (all portable: sm_80-level) -------------------
__device__ __forceinline__ uint32_t smem_u32(const void* p) {
    uint32_t a;
    asm("{ .reg .u64 t; cvta.to.shared.u64 t, %1; cvt.u32.u64 %0, t; }"
        : "=r"(a) : "l"(p));
    return a;
}
__device__ __forceinline__ void cp16(uint32_t dst, const void* src) {
    asm volatile("cp.async.cg.shared.global [%0], [%1], 16;"
                 :: "r"(dst), "l"(src) : "memory");
}
#define CP_COMMIT() asm volatile("cp.async.commit_group;" ::: "memory")
#define CP_WAIT1()  asm volatile("cp.async.wait_group 1;"  ::: "memory")

__device__ __forceinline__ void ldsm4(uint32_t* r, uint32_t addr) {
    asm volatile("ldmatrix.sync.aligned.m8n8.x4.shared.b16 {%0,%1,%2,%3}, [%4];"
                 : "=r"(r[0]), "=r"(r[1]), "=r"(r[2]), "=r"(r[3]) : "r"(addr));
}
__device__ __forceinline__ void mma_bf16(float* d, const uint32_t* a, const uint32_t* b) {
    asm volatile("mma.sync.aligned.m16n8k16.row.col.f32.bf16.bf16.f32 "
                 "{%0,%1,%2,%3}, {%4,%5,%6,%7}, {%8,%9}, {%0,%1,%2,%3};"
                 : "+f"(d[0]), "+f"(d[1]), "+f"(d[2]), "+f"(d[3])
                 : "r"(a[0]), "r"(a[1]), "r"(a[2]), "r"(a[3]),
                   "r"(b[0]), "r"(b[1]));
}
__device__ __forceinline__ uint32_t swz(uint32_t o) { return o ^ ((o >> 3) & 0x70); }

// ---------------- tile/stage layout ----------------------------------------
static constexpr int KC     = 64;        // bf16 k per chunk = 128B rows
static constexpr int OFF_AH = 0;         // 128 rows x 128B = 16KB per plane
static constexpr int OFF_AL = 16384;
static constexpr int OFF_BH = 32768;
static constexpr int OFF_BL = 49152;
static constexpr int STAGE  = 65536;     // 64KB per stage
static constexpr int SMEM_WM = 2 * STAGE;  // 128KB (double buffer)

// ---------------- pre-pass kernels ------------------------------------------
__global__ __launch_bounds__(256)
void k_split(const float* __restrict__ s, __nv_bfloat16* __restrict__ hi,
             __nv_bfloat16* __restrict__ lo, size_t n)
{
    size_t i = ((size_t)blockIdx.x * blockDim.x + threadIdx.x) * 4;
    if (i >= n) return;
    float4 v = *reinterpret_cast<const float4*>(s + i);
    __nv_bfloat16 h0 = __float2bfloat16(v.x), h1 = __float2bfloat16(v.y);
    __nv_bfloat16 h2 = __float2bfloat16(v.z), h3 = __float2bfloat16(v.w);
    __nv_bfloat16 l0 = __float2bfloat16(v.x - __bfloat162float(h0));
    __nv_bfloat16 l1 = __float2bfloat16(v.y - __bfloat162float(h1));
    __nv_bfloat16 l2 = __float2bfloat16(v.z - __bfloat162float(h2));
    __nv_bfloat16 l3 = __float2bfloat16(v.w - __bfloat162float(h3));
    __nv_bfloat162 a, b;
    a.x = h0; a.y = h1; b.x = h2; b.y = h3;
    reinterpret_cast<__nv_bfloat162*>(hi + i)[0] = a;
    reinterpret_cast<__nv_bfloat162*>(hi + i)[1] = b;
    a.x = l0; a.y = l1; b.x = l2; b.y = l3;
    reinterpret_cast<__nv_bfloat162*>(lo + i)[0] = a;
    reinterpret_cast<__nv_bfloat162*>(lo + i)[1] = b;
}

// support [NTOK,HID] fp32 -> supT hi/lo [HID,NTOK] bf16 (K-major for the GEMM)
__global__ __launch_bounds__(256)
void k_transpose_split(const float* __restrict__ S,
                       __nv_bfloat16* __restrict__ Th, __nv_bfloat16* __restrict__ Tl)
{
    __shared__ float t[32][33];
    const int tx = threadIdx.x & 31, ty = threadIdx.x >> 5;
    const int c0 = blockIdx.x * 32;   // over HID
    const int r0 = blockIdx.y * 32;   // over NTOK
    #pragma unroll
    for (int j = 0; j < 4; j++)
        t[ty + 8 * j][tx] = S[(size_t)(r0 + ty + 8 * j) * HID + c0 + tx];
    __syncthreads();
    #pragma unroll
    for (int j = 0; j < 4; j++) {
        float v = t[tx][ty + 8 * j];
        __nv_bfloat16 h = __float2bfloat16(v);
        __nv_bfloat16 l = __float2bfloat16(v - __bfloat162float(h));
        size_t o = (size_t)(c0 + ty + 8 * j) * NTOK + r0 + tx;
        Th[o] = h;  Tl[o] = l;
    }
}

// ---------------- SIMT GEMM for step 1 (x@W + b) ----------------------------
__global__ __launch_bounds__(256)
void gemm_128x64(const float* __restrict__ A, int lda,
                 const float* __restrict__ B, int ldb,
                 const float* __restrict__ bias,
                 float* __restrict__ C, int ldc, int K)
{
    __shared__ float As[16][128];
    __shared__ float Bs[16][64];
    const int tid = threadIdx.x;
    const int tx = tid & 15, ty = tid >> 4;
    const int bi = blockIdx.y * 128, bj = blockIdx.x * 64;
    const int ar = tid >> 1, ac = (tid & 1) * 8;
    const int bk = tid >> 4, bn = (tid & 15) * 4;

    float acc[8][4];
    #pragma unroll
    for (int i = 0; i < 8; i++)
        #pragma unroll
        for (int j = 0; j < 4; j++) acc[i][j] = 0.f;

    const float* Ap = A + (size_t)(bi + ar) * lda + ac;
    const float* Bp = B + (size_t)bk * ldb + bj + bn;

    for (int k0 = 0; k0 < K; k0 += 16) {
        float4 a0 = *(const float4*)(Ap + k0);
        float4 a1 = *(const float4*)(Ap + k0 + 4);
        float4 b0 = *(const float4*)(Bp + (size_t)k0 * ldb);
        As[ac + 0][ar] = a0.x; As[ac + 1][ar] = a0.y;
        As[ac + 2][ar] = a0.z; As[ac + 3][ar] = a0.w;
        As[ac + 4][ar] = a1.x; As[ac + 5][ar] = a1.y;
        As[ac + 6][ar] = a1.z; As[ac + 7][ar] = a1.w;
        *(float4*)&Bs[bk][bn] = b0;
        __syncthreads();
        #pragma unroll
        for (int k = 0; k < 16; k++) {
            float4 ra0 = *(const float4*)&As[k][ty * 8];
            float4 ra1 = *(const float4*)&As[k][ty * 8 + 4];
            float4 rb4 = *(const float4*)&Bs[k][tx * 4];
            float ra[8] = {ra0.x, ra0.y, ra0.z, ra0.w, ra1.x, ra1.y, ra1.z, ra1.w};
            float rb[4] = {rb4.x, rb4.y, rb4.z, rb4.w};
            #pragma unroll
            for (int i = 0; i < 8; i++)
                #pragma unroll
                for (int j = 0; j < 4; j++)
                    acc[i][j] = fmaf(ra[i], rb[j], acc[i][j]);
        }
        __syncthreads();
    }
    float4 bv = *(const float4*)&bias[bj + tx * 4];
    #pragma unroll
    for (int i = 0; i < 8; i++) {
        float4 v = {acc[i][0] + bv.x, acc[i][1] + bv.y, acc[i][2] + bv.z, acc[i][3] + bv.w};
        *(float4*)&C[(size_t)(bi + ty * 8 + i) * ldc + bj + tx * 4] = v;
    }
}

// ---------------- warp-MMA split-bf16 GEMM ----------------------------------
// D[128,128] tile = sum_k A[m][k] * B[n][k]; A,B split bf16 (hi+lo), f32 acc.
// 256 threads = 8 warps (2x4 grid), each warp 64x32 via m16n8k16 mma.sync.
// EPI 0: relu + re-split to bf16 hi/lo (h)      EPI 1: fp32 + symmetric mirror
template<int EPI>
__global__ __launch_bounds__(256, 1)
void wm_gemm(const __nv_bfloat16* __restrict__ Ah, const __nv_bfloat16* __restrict__ Al, int lda,
             const __nv_bfloat16* __restrict__ Bh, const __nv_bfloat16* __restrict__ Bl, int ldb,
             int K,
             __nv_bfloat16* __restrict__ OutHi, __nv_bfloat16* __restrict__ OutLo,
             float* __restrict__ C)
{
    if (EPI == 1 && blockIdx.x < blockIdx.y) return;   // upper triangle only

    extern __shared__ __align__(1024) char smem[];
    const uint32_t sbase = smem_u32(smem);
    const int tid  = threadIdx.x;
    const int lane = tid & 31, wid = tid >> 5;
    const int bi = blockIdx.y * 128;
    const int bj = blockIdx.x * 128;

    // ---- loader setup: threads 0-127 load A rows, 128-255 load B rows ----
    const int  lr  = tid & 127;
    const bool isB = tid >= 128;
    const __nv_bfloat16* srcH = isB ? Bh + (size_t)(bj + lr) * ldb
                                    : Ah + (size_t)(bi + lr) * lda;
    const __nv_bfloat16* srcL = isB ? Bl + (size_t)(bj + lr) * ldb
                                    : Al + (size_t)(bi + lr) * lda;
    const uint32_t offH = isB ? OFF_BH : OFF_AH;
    const uint32_t offL = isB ? OFF_BL : OFF_AL;

    auto load_stage = [&](int s, int k0) {
        const uint32_t stg = sbase + s * STAGE;
        #pragma unroll
        for (int u = 0; u < 8; u++) {
            uint32_t sw = swz((uint32_t)lr * 128u + u * 16u);
            cp16(stg + offH + sw, (const char*)(srcH + k0) + u * 16);
            cp16(stg + offL + sw, (const char*)(srcL + k0) + u * 16);
        }
    };

    // ---- per-lane ldmatrix address components ----
    const int mw = (wid >> 2) * 64;           // warp m-base within tile
    const int nw = (wid & 3) * 32;            // warp n-base within tile
    const uint32_t xm = (uint32_t)((lane & 7) << 4);
    uint32_t aoff[4], boff[2];
    {
        int ra = mw + (lane & 15);
        #pragma unroll
        for (int i = 0; i < 4; i++) aoff[i] = (uint32_t)(ra + 16 * i) * 128u;
        int rb = nw + (lane & 7) + ((lane >> 4) & 1) * 8;
        #pragma unroll
        for (int jj = 0; jj < 2; jj++) boff[jj] = (uint32_t)(rb + 16 * jj) * 128u;
    }
    const uint32_t koffA = (uint32_t)(((lane >> 4) & 1) * 16);
    const uint32_t koffB = (uint32_t)(((lane >> 3) & 1) * 16);

    float acc[4][4][4];
    #pragma unroll
    for (int i = 0; i < 4; i++)
        #pragma unroll
        for (int j = 0; j < 4; j++)
            #pragma unroll
            for (int q = 0; q < 4; q++) acc[i][j][q] = 0.f;

    auto compute = [&](int s) {
        const uint32_t stg = sbase + s * STAGE;
        #pragma unroll
        for (int ks = 0; ks < 4; ks++) {
            const uint32_t kb = (uint32_t)(ks * 32);
            uint32_t bh[4][2], bl[4][2];
            #pragma unroll
            for (int jj = 0; jj < 2; jj++) {
                uint32_t off = boff[jj] + ((kb + koffB) ^ xm);
                uint32_t r[4];
                ldsm4(r, stg + OFF_BH + off);
                bh[2*jj][0] = r[0]; bh[2*jj][1] = r[1];
                bh[2*jj+1][0] = r[2]; bh[2*jj+1][1] = r[3];
                ldsm4(r, stg + OFF_BL + off);
                bl[2*jj][0] = r[0]; bl[2*jj][1] = r[1];
                bl[2*jj+1][0] = r[2]; bl[2*jj+1][1] = r[3];
            }
            #pragma unroll
            for (int i = 0; i < 4; i++) {
                uint32_t offa = aoff[i] + ((kb + koffA) ^ xm);
                uint32_t ah[4], al[4];
                ldsm4(ah, stg + OFF_AH + offa);
                ldsm4(al, stg + OFF_AL + offa);
                #pragma unroll
                for (int j = 0; j < 4; j++) {
                    mma_bf16(acc[i][j], ah, bh[j]);   // hi*hi
                    mma_bf16(acc[i][j], ah, bl[j]);   // hi*lo
                    mma_bf16(acc[i][j], al, bh[j]);   // lo*hi
                }
            }
        }
    };

    // ---- 2-stage cp.async pipeline ----
    const int NC = K / KC;
    load_stage(0, 0);  CP_COMMIT();
    for (int mc = 0; mc < NC; mc++) {
        if (mc + 1 < NC) load_stage((mc + 1) & 1, (mc + 1) * KC);
        CP_COMMIT();
        CP_WAIT1();
        __syncthreads();
        compute(mc & 1);
        __syncthreads();
    }

    // ---- epilogue ----
    const int r0 = (lane >> 2);          // 0..7
    const int cl = (lane & 3) * 2;       // 0,2,4,6
    #pragma unroll
    for (int i = 0; i < 4; i++) {
        #pragma unroll
        for (int j = 0; j < 4; j++) {
            const int row0 = bi + mw + i * 16 + r0;
            const int row1 = row0 + 8;
            const int col  = bj + nw + j * 8 + cl;
            if (EPI == 0) {
                #pragma unroll
                for (int hhalf = 0; hhalf < 2; hhalf++) {
                    const int row = hhalf ? row1 : row0;
                    float v0 = fmaxf(acc[i][j][hhalf * 2 + 0], 0.f);
                    float v1 = fmaxf(acc[i][j][hhalf * 2 + 1], 0.f);
                    __nv_bfloat16 h0 = __float2bfloat16(v0), h1 = __float2bfloat16(v1);
                    __nv_bfloat16 l0 = __float2bfloat16(v0 - __bfloat162float(h0));
                    __nv_bfloat16 l1 = __float2bfloat16(v1 - __bfloat162float(h1));
                    __nv_bfloat162 ph; ph.x = h0; ph.y = h1;
                    __nv_bfloat162 pl; pl.x = l0; pl.y = l1;
                    size_t o = (size_t)row * HID + col;
                    *reinterpret_cast<__nv_bfloat162*>(OutHi + o) = ph;
                    *reinterpret_cast<__nv_bfloat162*>(OutLo + o) = pl;
                }
            } else {
                #pragma unroll
                for (int hhalf = 0; hhalf < 2; hhalf++) {
                    const int row = hhalf ? row1 : row0;
                    float v0 = acc[i][j][hhalf * 2 + 0];
                    float v1 = acc[i][j][hhalf * 2 + 1];
                    float2 v; v.x = v0; v.y = v1;
                    *reinterpret_cast<float2*>(C + (size_t)row * NTOK + col) = v;
                    if (blockIdx.x != blockIdx.y) {
                        C[(size_t)col * NTOK + row]       = v0;
                        C[(size_t)(col + 1) * NTOK + row] = v1;
                    }
                }
            }
        }
    }
}

// ---------------- launch -----------------------------------------------------
extern "C" void kernel_launch(void* const* d_in, const int* in_sizes, int n_in,
                              void* d_out, int out_size)
{
    const float* x   = (const float*)d_in[0];
    const float* adj = (const float*)d_in[1];
    const float* W   = (const float*)d_in[2];
    const float* b   = (const float*)d_in[3];
    float*       out = (float*)d_out;

    float *sup;
    __nv_bfloat16 *adjh, *adjl, *sth, *stl, *hh, *hl;
    cudaGetSymbolAddress((void**)&sup,  g_support);
    cudaGetSymbolAddress((void**)&adjh, g_adj_hi);
    cudaGetSymbolAddress((void**)&adjl, g_adj_lo);
    cudaGetSymbolAddress((void**)&sth,  g_supT_hi);
    cudaGetSymbolAddress((void**)&stl,  g_supT_lo);
    cudaGetSymbolAddress((void**)&hh,   g_h_hi);
    cudaGetSymbolAddress((void**)&hl,   g_h_lo);

    cudaFuncSetAttribute(wm_gemm<0>, cudaFuncAttributeMaxDynamicSharedMemorySize, SMEM_WM);
    cudaFuncSetAttribute(wm_gemm<1>, cudaFuncAttributeMaxDynamicSharedMemorySize, SMEM_WM);

    // 1) adj -> bf16 hi/lo split
    {
        size_t n = (size_t)NTOK * NTOK;
        int blocks = (int)((n / 4 + 255) / 256);
        k_split<<<blocks, 256>>>(adj, adjh, adjl, n);
    }
    // 2) support = x @ W + b   (fp32 SIMT)
    gemm_128x64<<<dim3(HID / 64, NTOK / 128), 256>>>(x, HID, W, HID, b, sup, HID, HID);
    // 3) supT hi/lo = split(transpose(support))
    k_transpose_split<<<dim3(HID / 32, NTOK / 32), 256>>>(sup, sth, stl);
    // 4) h = relu(adj @ support) -> bf16 hi/lo   (M=8192, N=256, K=8192)
    wm_gemm<0><<<dim3(HID / 128, NTOK / 128), 256, SMEM_WM>>>(
        adjh, adjl, NTOK, sth, stl, NTOK, NTOK, hh, hl, nullptr);
    // 5) out = h @ h^T   (M=N=8192, K=256, symmetric)
    wm_gemm<1><<<dim3(NTOK / 128, NTOK / 128), 256, SMEM_WM>>>(
        hh, hl, HID, hh, hl, HID, HID, nullptr, nullptr, out);
}

// round 8
// speedup vs baseline: 2.1361x; 1.2548x over previous
#include <cuda_runtime.h>
#include <cuda_bf16.h>
#include <cuda_fp16.h>
#include <cstdint>

static constexpr int NTOK = 8192;
static constexpr int HID  = 256;

// ---------------- scratch (device globals; no allocation allowed) -----------
__device__ __align__(256) float         g_support[NTOK * HID];
__device__ __align__(256) __nv_bfloat16 g_supT_hi[(size_t)HID * NTOK];
__device__ __align__(256) __nv_bfloat16 g_supT_lo[(size_t)HID * NTOK];
__device__ __align__(256) float         g_hpart[2 * (size_t)NTOK * HID];   // split-K partials
__device__ __align__(256) __half        g_hf16[(size_t)NTOK * HID];        // relu(h) in fp16

// ---------------- PTX helpers (portable sm_80-level) ------------------------
__device__ __forceinline__ uint32_t smem_u32(const void* p) {
    uint32_t a;
    asm("{ .reg .u64 t; cvta.to.shared.u64 t, %1; cvt.u32.u64 %0, t; }"
        : "=r"(a) : "l"(p));
    return a;
}
__device__ __forceinline__ void cp16(uint32_t dst, const void* src) {
    asm volatile("cp.async.cg.shared.global [%0], [%1], 16;"
                 :: "r"(dst), "l"(src) : "memory");
}
#define CP_COMMIT() asm volatile("cp.async.commit_group;" ::: "memory")
#define CP_WAIT0()  asm volatile("cp.async.wait_group 0;"  ::: "memory")
#define CP_WAIT1()  asm volatile("cp.async.wait_group 1;"  ::: "memory")

__device__ __forceinline__ void ldsm4(uint32_t* r, uint32_t addr) {
    asm volatile("ldmatrix.sync.aligned.m8n8.x4.shared.b16 {%0,%1,%2,%3}, [%4];"
                 : "=r"(r[0]), "=r"(r[1]), "=r"(r[2]), "=r"(r[3]) : "r"(addr));
}
__device__ __forceinline__ void mma_bf16(float* d, const uint32_t* a, const uint32_t* b) {
    asm volatile("mma.sync.aligned.m16n8k16.row.col.f32.bf16.bf16.f32 "
                 "{%0,%1,%2,%3}, {%4,%5,%6,%7}, {%8,%9}, {%0,%1,%2,%3};"
                 : "+f"(d[0]), "+f"(d[1]), "+f"(d[2]), "+f"(d[3])
                 : "r"(a[0]), "r"(a[1]), "r"(a[2]), "r"(a[3]), "r"(b[0]), "r"(b[1]));
}
__device__ __forceinline__ void mma_f16(float* d, const uint32_t* a, const uint32_t* b) {
    asm volatile("mma.sync.aligned.m16n8k16.row.col.f32.f16.f16.f32 "
                 "{%0,%1,%2,%3}, {%4,%5,%6,%7}, {%8,%9}, {%0,%1,%2,%3};"
                 : "+f"(d[0]), "+f"(d[1]), "+f"(d[2]), "+f"(d[3])
                 : "r"(a[0]), "r"(a[1]), "r"(a[2]), "r"(a[3]), "r"(b[0]), "r"(b[1]));
}
__device__ __forceinline__ uint32_t swz(uint32_t o) { return o ^ ((o >> 3) & 0x70); }

// ---------------- step 1: SIMT fp32 GEMM  support = x@W + b ------------------
__global__ __launch_bounds__(256)
void gemm_128x64(const float* __restrict__ A, int lda,
                 const float* __restrict__ B, int ldb,
                 const float* __restrict__ bias,
                 float* __restrict__ C, int ldc, int K)
{
    __shared__ float As[16][128];
    __shared__ float Bs[16][64];
    const int tid = threadIdx.x;
    const int tx = tid & 15, ty = tid >> 4;
    const int bi = blockIdx.y * 128, bj = blockIdx.x * 64;
    const int ar = tid >> 1, ac = (tid & 1) * 8;
    const int bk = tid >> 4, bn = (tid & 15) * 4;

    float acc[8][4];
    #pragma unroll
    for (int i = 0; i < 8; i++)
        #pragma unroll
        for (int j = 0; j < 4; j++) acc[i][j] = 0.f;

    const float* Ap = A + (size_t)(bi + ar) * lda + ac;
    const float* Bp = B + (size_t)bk * ldb + bj + bn;

    for (int k0 = 0; k0 < K; k0 += 16) {
        float4 a0 = *(const float4*)(Ap + k0);
        float4 a1 = *(const float4*)(Ap + k0 + 4);
        float4 b0 = *(const float4*)(Bp + (size_t)k0 * ldb);
        As[ac + 0][ar] = a0.x; As[ac + 1][ar] = a0.y;
        As[ac + 2][ar] = a0.z; As[ac + 3][ar] = a0.w;
        As[ac + 4][ar] = a1.x; As[ac + 5][ar] = a1.y;
        As[ac + 6][ar] = a1.z; As[ac + 7][ar] = a1.w;
        *(float4*)&Bs[bk][bn] = b0;
        __syncthreads();
        #pragma unroll
        for (int k = 0; k < 16; k++) {
            float4 ra0 = *(const float4*)&As[k][ty * 8];
            float4 ra1 = *(const float4*)&As[k][ty * 8 + 4];
            float4 rb4 = *(const float4*)&Bs[k][tx * 4];
            float ra[8] = {ra0.x, ra0.y, ra0.z, ra0.w, ra1.x, ra1.y, ra1.z, ra1.w};
            float rb[4] = {rb4.x, rb4.y, rb4.z, rb4.w};
            #pragma unroll
            for (int i = 0; i < 8; i++)
                #pragma unroll
                for (int j = 0; j < 4; j++)
                    acc[i][j] = fmaf(ra[i], rb[j], acc[i][j]);
        }
        __syncthreads();
    }
    float4 bv = *(const float4*)&bias[bj + tx * 4];
    #pragma unroll
    for (int i = 0; i < 8; i++) {
        float4 v = {acc[i][0] + bv.x, acc[i][1] + bv.y, acc[i][2] + bv.z, acc[i][3] + bv.w};
        *(float4*)&C[(size_t)(bi + ty * 8 + i) * ldc + bj + tx * 4] = v;
    }
}

// ---------------- step 2: support -> supT hi/lo (K-major bf16 split) ---------
__global__ __launch_bounds__(256)
void k_transpose_split(const float* __restrict__ S,
                       __nv_bfloat16* __restrict__ Th, __nv_bfloat16* __restrict__ Tl)
{
    __shared__ float t[32][33];
    const int tx = threadIdx.x & 31, ty = threadIdx.x >> 5;
    const int c0 = blockIdx.x * 32;   // over HID
    const int r0 = blockIdx.y * 32;   // over NTOK
    #pragma unroll
    for (int j = 0; j < 4; j++)
        t[ty + 8 * j][tx] = S[(size_t)(r0 + ty + 8 * j) * HID + c0 + tx];
    __syncthreads();
    #pragma unroll
    for (int j = 0; j < 4; j++) {
        float v = t[tx][ty + 8 * j];
        __nv_bfloat16 h = __float2bfloat16(v);
        __nv_bfloat16 l = __float2bfloat16(v - __bfloat162float(h));
        size_t o = (size_t)(c0 + ty + 8 * j) * NTOK + r0 + tx;
        Th[o] = h;  Tl[o] = l;
    }
}

// ---------------- step 3: GEMM2  h-partials = adj @ support ------------------
// Tile 128(M) x 256(N=full HID), split-K=2 -> 128 CTAs.
// adj loaded as fp32 via cp.async into staging, converted to bf16 hi/lo SMEM
// planes in-kernel (adj DRAM read exactly ONCE, no pre-split pass).
// B = supT hi/lo (8MB, L2-resident). bf16x3 split-precision MMA, fp32 partials.
static constexpr int G2_STG   = 0;                    // staging: 128 x 256B fp32
static constexpr int G2_S0    = 32768;                // stage base
static constexpr int G2_AH    = 0;                    // +16KB
static constexpr int G2_AL    = 16384;                // +16KB
static constexpr int G2_BH    = 32768;                // +32KB (256 rows)
static constexpr int G2_BL    = 65536;                // +32KB
static constexpr int G2_STAGE = 98304;                // 96KB per stage
static constexpr int G2_SMEM  = 32768 + 2 * G2_STAGE; // 229376 B

__global__ __launch_bounds__(256, 1)
void wm_gcn(const float* __restrict__ adj,
            const __nv_bfloat16* __restrict__ Bh, const __nv_bfloat16* __restrict__ Bl,
            float* __restrict__ P)
{
    extern __shared__ __align__(1024) char smem[];
    const uint32_t sb = smem_u32(smem);
    const int tid  = threadIdx.x;
    const int lane = tid & 31, wid = tid >> 5;
    const int bi   = blockIdx.y * 128;                 // M tile
    const int kbase = blockIdx.x * (NTOK / 2);         // K split half
    float* Pout = P + (size_t)blockIdx.x * NTOK * HID;

    // loader indices
    const int lr = tid >> 1, lh = tid & 1;             // A: row, half (32 floats)

    auto load_A_staging = [&](int k0) {                // adj fp32 -> staging (plain)
        const float* src = adj + (size_t)(bi + lr) * NTOK + kbase + k0 + lh * 32;
        const uint32_t dst = sb + G2_STG + (uint32_t)lr * 256u + (uint32_t)lh * 128u;
        #pragma unroll
        for (int u = 0; u < 8; u++) cp16(dst + u * 16, src + u * 4);
    };
    auto load_B = [&](int s, int k0) {                 // supT hi/lo, row = tid (0..255)
        const uint32_t stg = sb + G2_S0 + s * G2_STAGE;
        const __nv_bfloat16* sh = Bh + (size_t)tid * NTOK + kbase + k0;
        const __nv_bfloat16* sl = Bl + (size_t)tid * NTOK + kbase + k0;
        #pragma unroll
        for (int u = 0; u < 8; u++) {
            uint32_t sw = swz((uint32_t)tid * 128u + u * 16u);
            cp16(stg + G2_BH + sw, (const char*)sh + u * 16);
            cp16(stg + G2_BL + sw, (const char*)sl + u * 16);
        }
    };
    auto convert_A = [&](int s) {                      // staging fp32 -> hi/lo planes
        const uint32_t stg = sb + G2_S0 + s * G2_STAGE;
        const float* st = (const float*)(smem + G2_STG + lr * 256 + lh * 128);
        #pragma unroll
        for (int u = 0; u < 4; u++) {
            float4 f0 = ((const float4*)st)[2 * u];
            float4 f1 = ((const float4*)st)[2 * u + 1];
            float fv[8] = {f0.x, f0.y, f0.z, f0.w, f1.x, f1.y, f1.z, f1.w};
            uint32_t hw[4], lw[4];
            #pragma unroll
            for (int q = 0; q < 4; q++) {
                __nv_bfloat16 h0 = __float2bfloat16(fv[2 * q]);
                __nv_bfloat16 h1 = __float2bfloat16(fv[2 * q + 1]);
                __nv_bfloat16 l0 = __float2bfloat16(fv[2 * q] - __bfloat162float(h0));
                __nv_bfloat16 l1 = __float2bfloat16(fv[2 * q + 1] - __bfloat162float(h1));
                __nv_bfloat162 ph; ph.x = h0; ph.y = h1;
                __nv_bfloat162 pl; pl.x = l0; pl.y = l1;
                hw[q] = *(uint32_t*)&ph;  lw[q] = *(uint32_t*)&pl;
            }
            uint32_t sw = swz((uint32_t)lr * 128u + (uint32_t)lh * 64u + u * 16u);
            *(uint4*)(smem + (stg - sb) + G2_AH + sw) = make_uint4(hw[0], hw[1], hw[2], hw[3]);
            *(uint4*)(smem + (stg - sb) + G2_AL + sw) = make_uint4(lw[0], lw[1], lw[2], lw[3]);
        }
    };

    // warp microtile: 2(M) x 4(N) warps, each 64 x 64
    const int mw = (wid >> 2) * 64;
    const int nw = (wid & 3) * 64;
    const uint32_t xm = (uint32_t)((lane & 7) << 4);
    uint32_t aoff[4], boff[4];
    {
        int ra = mw + (lane & 15);
        #pragma unroll
        for (int i = 0; i < 4; i++) aoff[i] = (uint32_t)(ra + 16 * i) * 128u;
        int rb = nw + (lane & 7) + ((lane >> 4) & 1) * 8;
        #pragma unroll
        for (int jj = 0; jj < 4; jj++) boff[jj] = (uint32_t)(rb + 16 * jj) * 128u;
    }
    const uint32_t koffA = (uint32_t)(((lane >> 4) & 1) * 16);
    const uint32_t koffB = (uint32_t)(((lane >> 3) & 1) * 16);

    float acc[4][8][4];
    #pragma unroll
    for (int i = 0; i < 4; i++)
        #pragma unroll
        for (int j = 0; j < 8; j++)
            #pragma unroll
            for (int q = 0; q < 4; q++) acc[i][j][q] = 0.f;

    auto compute = [&](int s) {
        const uint32_t stg = sb + G2_S0 + s * G2_STAGE;
        #pragma unroll
        for (int ks = 0; ks < 4; ks++) {
            const uint32_t kb = (uint32_t)(ks * 32);
            uint32_t bh[8][2], bl[8][2];
            #pragma unroll
            for (int jj = 0; jj < 4; jj++) {
                uint32_t off = boff[jj] + ((kb + koffB) ^ xm);
                uint32_t r[4];
                ldsm4(r, stg + G2_BH + off);
                bh[2*jj][0] = r[0]; bh[2*jj][1] = r[1];
                bh[2*jj+1][0] = r[2]; bh[2*jj+1][1] = r[3];
                ldsm4(r, stg + G2_BL + off);
                bl[2*jj][0] = r[0]; bl[2*jj][1] = r[1];
                bl[2*jj+1][0] = r[2]; bl[2*jj+1][1] = r[3];
            }
            #pragma unroll
            for (int i = 0; i < 4; i++) {
                uint32_t offa = aoff[i] + ((kb + koffA) ^ xm);
                uint32_t ah[4], al[4];
                ldsm4(ah, stg + G2_AH + offa);
                ldsm4(al, stg + G2_AL + offa);
                #pragma unroll
                for (int j = 0; j < 8; j++) {
                    mma_bf16(acc[i][j], ah, bh[j]);
                    mma_bf16(acc[i][j], ah, bl[j]);
                    mma_bf16(acc[i][j], al, bh[j]);
                }
            }
        }
    };

    // mainloop: KC=64, NC = 4096/64 = 64
    const int NC = (NTOK / 2) / 64;
    load_B(0, 0);  load_A_staging(0);  CP_COMMIT();
    for (int mc = 0; mc < NC; mc++) {
        const int s = mc & 1;
        CP_WAIT0();
        __syncthreads();
        convert_A(s);
        __syncthreads();
        if (mc + 1 < NC) { load_B(s ^ 1, (mc + 1) * 64); load_A_staging((mc + 1) * 64); }
        CP_COMMIT();
        compute(s);
    }

    // epilogue: fp32 partials, coalesced float2 stores
    const int r0 = (lane >> 2);
    const int cl = (lane & 3) * 2;
    #pragma unroll
    for (int i = 0; i < 4; i++)
        #pragma unroll
        for (int j = 0; j < 8; j++)
            #pragma unroll
            for (int hf = 0; hf < 2; hf++) {
                const int row = bi + mw + i * 16 + r0 + hf * 8;
                const int col = nw + j * 8 + cl;
                float2 v; v.x = acc[i][j][hf * 2]; v.y = acc[i][j][hf * 2 + 1];
                *reinterpret_cast<float2*>(Pout + (size_t)row * HID + col) = v;
            }
}

// ---------------- step 4: reduce partials + relu -> fp16 h -------------------
__global__ __launch_bounds__(256)
void k_reduce_relu_f16(const float* __restrict__ P, __half* __restrict__ H)
{
    size_t i = ((size_t)blockIdx.x * blockDim.x + threadIdx.x) * 4;
    const float* p0 = P;
    const float* p1 = P + (size_t)NTOK * HID;
    float4 a = *reinterpret_cast<const float4*>(p0 + i);
    float4 b = *reinterpret_cast<const float4*>(p1 + i);
    float v0 = fmaxf(a.x + b.x, 0.f), v1 = fmaxf(a.y + b.y, 0.f);
    float v2 = fmaxf(a.z + b.z, 0.f), v3 = fmaxf(a.w + b.w, 0.f);
    __half2 h0 = __floats2half2_rn(v0, v1);
    __half2 h1 = __floats2half2_rn(v2, v3);
    uint2 w; w.x = *(uint32_t*)&h0; w.y = *(uint32_t*)&h1;
    *reinterpret_cast<uint2*>(H + i) = w;
}

// ---------------- step 5: SYRK  out = h @ h^T  (fp16 1-term) -----------------
// 128x128 tiles, upper triangle; mirror via SMEM transpose (coalesced).
static constexpr int SK_STAGE = 32768;                        // A 16KB + B 16KB
static constexpr int SK_SMEM  = 128 * 132 * 4;                // 67584 (>= 2*SK_STAGE)

__global__ __launch_bounds__(256, 1)
void wm_syrk(const __half* __restrict__ H, float* __restrict__ C)
{
    if (blockIdx.x < blockIdx.y) return;   // upper triangle only

    extern __shared__ __align__(1024) char smem[];
    const uint32_t sb = smem_u32(smem);
    const int tid  = threadIdx.x;
    const int lane = tid & 31, wid = tid >> 5;
    const int bi = blockIdx.y * 128;
    const int bj = blockIdx.x * 128;

    const int  lr  = tid & 127;
    const bool isB = tid >= 128;
    const __half* src = H + (size_t)((isB ? bj : bi) + lr) * HID;
    const uint32_t pofs = isB ? 16384u : 0u;

    auto load_stage = [&](int s, int k0) {
        const uint32_t stg = sb + s * SK_STAGE + pofs;
        #pragma unroll
        for (int u = 0; u < 8; u++) {
            uint32_t sw = swz((uint32_t)lr * 128u + u * 16u);
            cp16(stg + sw, (const char*)(src + k0) + u * 16);
        }
    };

    const int mw = (wid >> 2) * 64;
    const int nw = (wid & 3) * 32;
    const uint32_t xm = (uint32_t)((lane & 7) << 4);
    uint32_t aoff[4], boff[2];
    {
        int ra = mw + (lane & 15);
        #pragma unroll
        for (int i = 0; i < 4; i++) aoff[i] = (uint32_t)(ra + 16 * i) * 128u;
        int rb = nw + (lane & 7) + ((lane >> 4) & 1) * 8;
        #pragma unroll
        for (int jj = 0; jj < 2; jj++) boff[jj] = (uint32_t)(rb + 16 * jj) * 128u;
    }
    const uint32_t koffA = (uint32_t)(((lane >> 4) & 1) * 16);
    const uint32_t koffB = (uint32_t)(((lane >> 3) & 1) * 16);

    float acc[4][4][4];
    #pragma unroll
    for (int i = 0; i < 4; i++)
        #pragma unroll
        for (int j = 0; j < 4; j++)
            #pragma unroll
            for (int q = 0; q < 4; q++) acc[i][j][q] = 0.f;

    auto compute = [&](int s) {
        const uint32_t stg = sb + s * SK_STAGE;
        #pragma unroll
        for (int ks = 0; ks < 4; ks++) {
            const uint32_t kb = (uint32_t)(ks * 32);
            uint32_t bfr[4][2];
            #pragma unroll
            for (int jj = 0; jj < 2; jj++) {
                uint32_t r[4];
                ldsm4(r, stg + 16384u + boff[jj] + ((kb + koffB) ^ xm));
                bfr[2*jj][0] = r[0]; bfr[2*jj][1] = r[1];
                bfr[2*jj+1][0] = r[2]; bfr[2*jj+1][1] = r[3];
            }
            #pragma unroll
            for (int i = 0; i < 4; i++) {
                uint32_t afr[4];
                ldsm4(afr, stg + aoff[i] + ((kb + koffA) ^ xm));
                #pragma unroll
                for (int j = 0; j < 4; j++) mma_f16(acc[i][j], afr, bfr[j]);
            }
        }
    };

    // K = 256 -> NC = 4, two-stage pipeline
    load_stage(0, 0);  CP_COMMIT();
    for (int mc = 0; mc < 4; mc++) {
        if (mc + 1 < 4) load_stage((mc + 1) & 1, (mc + 1) * 64);
        CP_COMMIT();
        CP_WAIT1();
        __syncthreads();
        compute(mc & 1);
        __syncthreads();
    }

    // direct stores (upper-tri block region)
    const int r0 = (lane >> 2);
    const int cl = (lane & 3) * 2;
    #pragma unroll
    for (int i = 0; i < 4; i++)
        #pragma unroll
        for (int j = 0; j < 4; j++)
            #pragma unroll
            for (int hf = 0; hf < 2; hf++) {
                const int row = bi + mw + i * 16 + r0 + hf * 8;
                const int col = bj + nw + j * 8 + cl;
                float2 v; v.x = acc[i][j][hf * 2]; v.y = acc[i][j][hf * 2 + 1];
                *reinterpret_cast<float2*>(C + (size_t)row * NTOK + col) = v;
            }

    // coalesced mirror via SMEM transpose (reuses stage memory; compute done)
    if (blockIdx.x != blockIdx.y) {
        float* tr = (float*)smem;                 // [col][row], pitch 132
        #pragma unroll
        for (int i = 0; i < 4; i++)
            #pragma unroll
            for (int j = 0; j < 4; j++)
                #pragma unroll
                for (int hf = 0; hf < 2; hf++) {
                    const int row = mw + i * 16 + r0 + hf * 8;
                    const int col = nw + j * 8 + cl;
                    tr[(col)     * 132 + row] = acc[i][j][hf * 2];
                    tr[(col + 1) * 132 + row] = acc[i][j][hf * 2 + 1];
                }
        __syncthreads();
        const int c = tid >> 1, hh = tid & 1;
        const float* srcr = tr + c * 132 + hh * 64;
        float* dst = C + (size_t)(bj + c) * NTOK + bi + hh * 64;
        #pragma unroll
        for (int u = 0; u < 16; u++)
            *reinterpret_cast<float4*>(dst + u * 4) = ((const float4*)srcr)[u];
    }
}

// ---------------- launch -----------------------------------------------------
extern "C" void kernel_launch(void* const* d_in, const int* in_sizes, int n_in,
                              void* d_out, int out_size)
{
    const float* x   = (const float*)d_in[0];
    const float* adj = (const float*)d_in[1];
    const float* W   = (const float*)d_in[2];
    const float* b   = (const float*)d_in[3];
    float*       out = (float*)d_out;

    float *sup, *hp;
    __nv_bfloat16 *sth, *stl;
    __half *hf;
    cudaGetSymbolAddress((void**)&sup, g_support);
    cudaGetSymbolAddress((void**)&sth, g_supT_hi);
    cudaGetSymbolAddress((void**)&stl, g_supT_lo);
    cudaGetSymbolAddress((void**)&hp,  g_hpart);
    cudaGetSymbolAddress((void**)&hf,  g_hf16);

    cudaFuncSetAttribute(wm_gcn,  cudaFuncAttributeMaxDynamicSharedMemorySize, G2_SMEM);
    cudaFuncSetAttribute(wm_syrk, cudaFuncAttributeMaxDynamicSharedMemorySize, SK_SMEM);

    // 1) support = x @ W + b
    gemm_128x64<<<dim3(HID / 64, NTOK / 128), 256>>>(x, HID, W, HID, b, sup, HID, HID);
    // 2) supT hi/lo
    k_transpose_split<<<dim3(HID / 32, NTOK / 32), 256>>>(sup, sth, stl);
    // 3) h-partials = adj @ support  (fused fp32->bf16x2 convert, split-K=2)
    wm_gcn<<<dim3(2, NTOK / 128), 256, G2_SMEM>>>(adj, sth, stl, hp);
    // 4) h = relu(p0 + p1) -> fp16
    k_reduce_relu_f16<<<(NTOK * HID / 4) / 256, 256>>>(hp, hf);
    // 5) out = h @ h^T  (fp16, symmetric)
    wm_syrk<<<dim3(NTOK / 128, NTOK / 128), 256, SK_SMEM>>>(hf, out);
}